// round 1
// baseline (speedup 1.0000x reference)
#include <cuda_runtime.h>
#include <math.h>

// Problem constants
#define BB 128      // batch
#define TT 256      // time steps
#define HH 1024     // hidden
#define NCTA 128    // persistent grid (must be <= SM count for residency)
#define NTHR 256
#define NSPLIT 16   // K-splits
#define BK 16       // k-chunk staged in smem
#define SMSTRIDE 132  // padded smem row stride (mult of 4 for float4 alignment)

// Scratch (device globals: allocation-free rule)
__device__ float g_xp[(size_t)TT * BB * HH];          // [t][b][n] = x@Wi0 + bi0
__device__ float g_h0[2][BB * HH];                    // layer-0 hidden ping-pong
__device__ float g_h1[2][BB * HH];                    // layer-1 hidden ping-pong
__device__ float g_part[NSPLIT][BB * HH];             // split-K partial sums
__device__ unsigned g_cnt;                            // barrier arrive count (zero-init)
__device__ volatile unsigned g_gen;                   // barrier generation (zero-init)

// ---------------------------------------------------------------------------
// Grid-wide barrier. Safe because all NCTA CTAs are co-resident (occ >= 1).
// Release/acquire via threadfence + L2-level (volatile) generation flag.
// ---------------------------------------------------------------------------
__device__ __forceinline__ void grid_sync() {
    __syncthreads();
    if (threadIdx.x == 0) {
        unsigned my = g_gen;
        __threadfence();  // release: make this CTA's global writes visible
        if (atomicAdd(&g_cnt, 1u) == gridDim.x - 1) {
            g_cnt = 0;
            __threadfence();
            g_gen = my + 1;
        } else {
            while (g_gen == my) { }
        }
    }
    __syncthreads();
}

// ---------------------------------------------------------------------------
// 128x128 output tile GEMM core, 256 threads, 8x8 per thread, BK=16 chunks.
// A: row-major [*, HH], column window pre-offset by caller (aptr0 at row m0=tid/4,
//    aptr1 at row m0+64). W: row-major [*, HH], pre-offset to (koff + tid/32, n0 + (tid%32)*4).
// A_LDCG: load A with .cg (L2) — required for cross-CTA coherence in the
// persistent kernel.
// ---------------------------------------------------------------------------
template <bool A_LDCG>
__device__ __forceinline__ void gemm_core(
    float c[64],
    const float* aptr0, const float* aptr1,
    const float* wptr,
    int nchunks,
    float* As, float* Bs)
{
    const int tid  = threadIdx.x;
    const int tx   = tid & 15;
    const int ty   = tid >> 4;
    const int la_m = tid >> 2;
    const int la_k = (tid & 3) << 2;
    const int lb_k = tid >> 5;
    const int lb_n = (tid & 31) << 2;

    for (int ch = 0; ch < nchunks; ch++) {
        float4 a0, a1;
        if (A_LDCG) {
            a0 = __ldcg((const float4*)aptr0);
            a1 = __ldcg((const float4*)aptr1);
        } else {
            a0 = *(const float4*)aptr0;
            a1 = *(const float4*)aptr1;
        }
        float4 b0 = *(const float4*)wptr;
        float4 b1 = *(const float4*)(wptr + 8 * HH);

        __syncthreads();  // previous chunk's compute done before overwrite
        As[(la_k + 0) * SMSTRIDE + la_m] = a0.x;
        As[(la_k + 1) * SMSTRIDE + la_m] = a0.y;
        As[(la_k + 2) * SMSTRIDE + la_m] = a0.z;
        As[(la_k + 3) * SMSTRIDE + la_m] = a0.w;
        As[(la_k + 0) * SMSTRIDE + la_m + 64] = a1.x;
        As[(la_k + 1) * SMSTRIDE + la_m + 64] = a1.y;
        As[(la_k + 2) * SMSTRIDE + la_m + 64] = a1.z;
        As[(la_k + 3) * SMSTRIDE + la_m + 64] = a1.w;
        *(float4*)(Bs + lb_k * SMSTRIDE + lb_n)       = b0;
        *(float4*)(Bs + (lb_k + 8) * SMSTRIDE + lb_n) = b1;
        __syncthreads();

        #pragma unroll
        for (int kk = 0; kk < BK; kk++) {
            float a[8], b[8];
            *(float4*)&a[0] = *(const float4*)(As + kk * SMSTRIDE + ty * 8);
            *(float4*)&a[4] = *(const float4*)(As + kk * SMSTRIDE + ty * 8 + 4);
            *(float4*)&b[0] = *(const float4*)(Bs + kk * SMSTRIDE + tx * 8);
            *(float4*)&b[4] = *(const float4*)(Bs + kk * SMSTRIDE + tx * 8 + 4);
            #pragma unroll
            for (int i = 0; i < 8; i++)
                #pragma unroll
                for (int j = 0; j < 8; j++)
                    c[i * 8 + j] += a[i] * b[j];
        }
        aptr0 += BK;
        aptr1 += BK;
        wptr  += BK * HH;
    }
}

// ---------------------------------------------------------------------------
// Kernel 1: Xp[t][b][:] = x[b][t][:] @ Wi0 + bi0   (row r = t*B + b)
// Grid: (8 n-tiles, 256 m-tiles), 256 threads, tile 128x128, K=1024.
// ---------------------------------------------------------------------------
__global__ void __launch_bounds__(NTHR)
xp_kernel(const float* __restrict__ x,
          const float* __restrict__ Wi,
          const float* __restrict__ bi)
{
    __shared__ float As[BK * SMSTRIDE];
    __shared__ float Bs[BK * SMSTRIDE];

    const int tid = threadIdx.x;
    const int n0  = blockIdx.x * 128;
    const int r0  = blockIdx.y * 128;

    const int m0 = tid >> 2;
    const int ka = (tid & 3) << 2;
    const int r_a0 = r0 + m0;
    const int r_a1 = r_a0 + 64;
    // r = t*B + b  ->  b = r & 127, t = r >> 7 ; x index = (b*T + t)*H + k
    const float* aptr0 = x + (size_t)((r_a0 & (BB - 1)) * TT + (r_a0 >> 7)) * HH + ka;
    const float* aptr1 = x + (size_t)((r_a1 & (BB - 1)) * TT + (r_a1 >> 7)) * HH + ka;
    const float* wptr  = Wi + (size_t)(tid >> 5) * HH + n0 + ((tid & 31) << 2);

    float c[64];
    #pragma unroll
    for (int i = 0; i < 64; i++) c[i] = 0.f;

    gemm_core<false>(c, aptr0, aptr1, wptr, HH / BK, As, Bs);

    const int tx = tid & 15, ty = tid >> 4;
    float bv[8];
    #pragma unroll
    for (int j = 0; j < 8; j++) bv[j] = bi[n0 + tx * 8 + j];

    #pragma unroll
    for (int i = 0; i < 8; i++) {
        const int r = r0 + ty * 8 + i;
        float* dst = g_xp + (size_t)r * HH + n0 + tx * 8;
        float4 v0 = make_float4(c[i*8+0] + bv[0], c[i*8+1] + bv[1],
                                c[i*8+2] + bv[2], c[i*8+3] + bv[3]);
        float4 v1 = make_float4(c[i*8+4] + bv[4], c[i*8+5] + bv[5],
                                c[i*8+6] + bv[6], c[i*8+7] + bv[7]);
        *(float4*)dst       = v0;
        *(float4*)(dst + 4) = v1;
    }
}

// ---------------------------------------------------------------------------
// Kernel 2: persistent recurrent kernel. 128 CTAs x 256 threads.
// Per step: L0 split-K partials -> sync -> L0 reduce+tanh -> sync ->
//           L1 split-K partials (virtual K=2048 over [h0;h1prev]) -> sync ->
//           L1 reduce+tanh (write output) -> sync.
// ---------------------------------------------------------------------------
__global__ void __launch_bounds__(NTHR)
rnn_kernel(const float* __restrict__ h0in,
           const float* __restrict__ Wi,
           const float* __restrict__ bi,
           const float* __restrict__ Wh,
           const float* __restrict__ bh,
           float* __restrict__ out)
{
    __shared__ float As[BK * SMSTRIDE];
    __shared__ float Bs[BK * SMSTRIDE];

    const int tid   = threadIdx.x;
    const int cta   = blockIdx.x;
    const int gtid  = cta * NTHR + tid;       // 0..32767
    const int ntile = cta & 7;                // 8 n-tiles of 128
    const int split = cta >> 3;               // 16 k-splits
    const int n0    = ntile * 128;
    const int tx    = tid & 15, ty = tid >> 4;
    const int m0    = tid >> 2;
    const int ka    = (tid & 3) << 2;

    // init hidden state: broadcast h0in over batch
    for (int e = gtid; e < BB * HH; e += NCTA * NTHR) {
        const int hc = e & (HH - 1);
        g_h0[0][e] = h0in[hc];
        g_h1[0][e] = h0in[HH + hc];
    }
    grid_sync();

    for (int t = 0; t < TT; t++) {
        const int prev = t & 1;
        const int cur  = prev ^ 1;

        // ---- L0 partial: h0_prev @ Wh0, K slice [split*64, +64) ----
        {
            const int koff = split * 64;
            const float* A   = g_h0[prev];
            const float* ap0 = A + (size_t)m0 * HH + koff + ka;
            const float* ap1 = ap0 + (size_t)64 * HH;
            const float* wp  = Wh + (size_t)(koff + (tid >> 5)) * HH + n0 + ((tid & 31) << 2);
            float c[64];
            #pragma unroll
            for (int i = 0; i < 64; i++) c[i] = 0.f;
            gemm_core<true>(c, ap0, ap1, wp, 64 / BK, As, Bs);
            float* dst = g_part[split] + (size_t)(ty * 8) * HH + n0 + tx * 8;
            #pragma unroll
            for (int i = 0; i < 8; i++) {
                *(float4*)(dst + (size_t)i * HH)     = make_float4(c[i*8+0], c[i*8+1], c[i*8+2], c[i*8+3]);
                *(float4*)(dst + (size_t)i * HH + 4) = make_float4(c[i*8+4], c[i*8+5], c[i*8+6], c[i*8+7]);
            }
        }
        grid_sync();

        // ---- L0 reduce: h0_cur = tanh(Xp[t] + bh0 + sum partials) ----
        {
            const int e = gtid * 4;
            const int n = e & (HH - 1);
            float4 acc = *(const float4*)(g_xp + (size_t)t * BB * HH + e);
            acc.x += bh[n];     acc.y += bh[n + 1];
            acc.z += bh[n + 2]; acc.w += bh[n + 3];
            #pragma unroll
            for (int s = 0; s < NSPLIT; s++) {
                float4 p = __ldcg((const float4*)(g_part[s] + e));
                acc.x += p.x; acc.y += p.y; acc.z += p.z; acc.w += p.w;
            }
            float4 r = make_float4(tanhf(acc.x), tanhf(acc.y), tanhf(acc.z), tanhf(acc.w));
            *(float4*)(g_h0[cur] + e) = r;
        }
        grid_sync();

        // ---- L1 partial: virtual K=2048 over [h0_cur @ Wi1 ; h1_prev @ Wh1] ----
        {
            const float* A;
            const float* W;
            int koff;
            if (split < 8) { A = g_h0[cur];  W = Wi + (size_t)HH * HH; koff = split * 128; }
            else           { A = g_h1[prev]; W = Wh + (size_t)HH * HH; koff = (split - 8) * 128; }
            const float* ap0 = A + (size_t)m0 * HH + koff + ka;
            const float* ap1 = ap0 + (size_t)64 * HH;
            const float* wp  = W + (size_t)(koff + (tid >> 5)) * HH + n0 + ((tid & 31) << 2);
            float c[64];
            #pragma unroll
            for (int i = 0; i < 64; i++) c[i] = 0.f;
            gemm_core<true>(c, ap0, ap1, wp, 128 / BK, As, Bs);
            float* dst = g_part[split] + (size_t)(ty * 8) * HH + n0 + tx * 8;
            #pragma unroll
            for (int i = 0; i < 8; i++) {
                *(float4*)(dst + (size_t)i * HH)     = make_float4(c[i*8+0], c[i*8+1], c[i*8+2], c[i*8+3]);
                *(float4*)(dst + (size_t)i * HH + 4) = make_float4(c[i*8+4], c[i*8+5], c[i*8+6], c[i*8+7]);
            }
        }
        grid_sync();

        // ---- L1 reduce: h1_cur = tanh(bi1 + bh1 + sum partials); write output ----
        {
            const int e = gtid * 4;
            const int n = e & (HH - 1);
            const int b = e >> 10;
            float4 acc;
            acc.x = bi[HH + n]     + bh[HH + n];
            acc.y = bi[HH + n + 1] + bh[HH + n + 1];
            acc.z = bi[HH + n + 2] + bh[HH + n + 2];
            acc.w = bi[HH + n + 3] + bh[HH + n + 3];
            #pragma unroll
            for (int s = 0; s < NSPLIT; s++) {
                float4 p = __ldcg((const float4*)(g_part[s] + e));
                acc.x += p.x; acc.y += p.y; acc.z += p.z; acc.w += p.w;
            }
            float4 r = make_float4(tanhf(acc.x), tanhf(acc.y), tanhf(acc.z), tanhf(acc.w));
            *(float4*)(g_h1[cur] + e) = r;
            *(float4*)(out + ((size_t)b * TT + t) * HH + n) = r;
        }
        grid_sync();
    }

    // finals: h_n[b][0][:] = h0 final, h_n[b][1][:] = h1 final (both in buffer 0
    // since cur at t=255 is 0). Use .cg loads: written by other CTAs.
    float* hn = out + (size_t)BB * TT * HH;
    for (int e = gtid; e < BB * HH; e += NCTA * NTHR) {
        const int b = e >> 10;
        const int n = e & (HH - 1);
        hn[(size_t)(b * 2) * HH + n]     = __ldcg(g_h0[0] + e);
        hn[(size_t)(b * 2 + 1) * HH + n] = __ldcg(g_h1[0] + e);
    }
}

// ---------------------------------------------------------------------------
// Entry point
// ---------------------------------------------------------------------------
extern "C" void kernel_launch(void* const* d_in, const int* in_sizes, int n_in,
                              void* d_out, int out_size)
{
    const float* x    = (const float*)d_in[0];
    const float* h0in = (const float*)d_in[1];
    const float* Wi   = (const float*)d_in[2];
    const float* bi   = (const float*)d_in[3];
    const float* Wh   = (const float*)d_in[4];
    const float* bh   = (const float*)d_in[5];
    float* out = (float*)d_out;

    dim3 gx(HH / 128, (BB * TT) / 128);   // (8, 256)
    xp_kernel<<<gx, NTHR>>>(x, Wi, bi);
    rnn_kernel<<<NCTA, NTHR>>>(h0in, Wi, bi, Wh, bh, out);
}

// round 10
// speedup vs baseline: 1.6406x; 1.6406x over previous
#include <cuda_runtime.h>
#include <cuda_bf16.h>
#include <math.h>
#include <stdint.h>

// ---------------- problem constants ----------------
#define BB 128      // batch
#define TT 256      // time steps
#define HH 1024     // hidden
#define NCTA 128    // persistent grid
#define NTHR 256
#define NSPLIT 16   // k-splits (64 k per split)
#define TSTRIDE 144 // smem tile row stride in bytes (72 bf16): conflict-free ldmatrix

// ---------------- device scratch (allocation-free rule) ----------------
__device__ float g_xp[(size_t)TT * BB * HH];               // x@Wi0 + bi0, [t*B+b][n]
__device__ float g_h0[2][BB * HH];
__device__ float g_h1[2][BB * HH];
__device__ float g_part[NSPLIT][BB * HH];
__device__ __nv_bfloat16 g_wt_hi[4][HH * HH];              // W^T bf16 hi: 0=Wi0,1=Wh0,2=Wi1,3=Wh1
__device__ __nv_bfloat16 g_wt_lo[4][HH * HH];              // W^T bf16 lo
__device__ __nv_bfloat16 g_xs_hi[(size_t)TT * BB * HH];    // x split, [t*B+b][k]
__device__ __nv_bfloat16 g_xs_lo[(size_t)TT * BB * HH];
__device__ unsigned g_cnt;
__device__ volatile unsigned g_gen;

// ---------------- helpers ----------------
__device__ __forceinline__ uint32_t smem_u32(const void* p) {
    uint32_t a;
    asm("{ .reg .u64 t; cvta.to.shared.u64 t, %1; cvt.u32.u64 %0, t; }" : "=r"(a) : "l"(p));
    return a;
}

__device__ __forceinline__ void ldsm4(uint32_t* r, uint32_t addr) {
    asm volatile("ldmatrix.sync.aligned.m8n8.x4.shared.b16 {%0,%1,%2,%3}, [%4];"
                 : "=r"(r[0]), "=r"(r[1]), "=r"(r[2]), "=r"(r[3]) : "r"(addr));
}

__device__ __forceinline__ void mma16816(float* d, const uint32_t* a, const uint32_t* b) {
    asm volatile(
        "mma.sync.aligned.m16n8k16.row.col.f32.bf16.bf16.f32 "
        "{%0,%1,%2,%3}, {%4,%5,%6,%7}, {%8,%9}, {%0,%1,%2,%3};"
        : "+f"(d[0]), "+f"(d[1]), "+f"(d[2]), "+f"(d[3])
        : "r"(a[0]), "r"(a[1]), "r"(a[2]), "r"(a[3]), "r"(b[0]), "r"(b[1]));
}

// ---------------- grid barrier (all NCTA CTAs co-resident, occ=1 via smem) ----
__device__ __forceinline__ void grid_sync() {
    __syncthreads();
    if (threadIdx.x == 0) {
        unsigned my = g_gen;
        __threadfence();
        if (atomicAdd(&g_cnt, 1u) == gridDim.x - 1) {
            g_cnt = 0;
            __threadfence();
            g_gen = my + 1;
        } else {
            while (g_gen == my) { }
        }
    }
    __syncthreads();
}

// ---------------- bf16 hi/lo split ----------------
__device__ __forceinline__ void bsplit(float f, unsigned short& h, unsigned short& l) {
    __nv_bfloat16 hb = __float2bfloat16(f);
    float rem = f - __bfloat162float(hb);
    __nv_bfloat16 lb = __float2bfloat16(rem);
    h = __bfloat16_as_ushort(hb);
    l = __bfloat16_as_ushort(lb);
}

// ---------------- smem tile fills (tile: 128 rows x 64 bf16, stride 144B) ----
// from fp32 global (stride HH), split into hi/lo
__device__ __forceinline__ void fill_A(char* sm, int offH, int offL,
                                       const float* src, int koff) {
    const int tid = threadIdx.x;
    const int row = tid >> 1;
    const int kh  = (tid & 1) * 32;
    const float4* p = (const float4*)(src + (size_t)row * HH + koff + kh);
    unsigned hi[16], lo[16];
    #pragma unroll
    for (int i = 0; i < 8; i++) {
        float4 v = __ldcg(p + i);
        unsigned short h0, l0, h1, l1, h2, l2, h3, l3;
        bsplit(v.x, h0, l0); bsplit(v.y, h1, l1);
        bsplit(v.z, h2, l2); bsplit(v.w, h3, l3);
        hi[i*2]   = (unsigned)h0 | ((unsigned)h1 << 16);
        hi[i*2+1] = (unsigned)h2 | ((unsigned)h3 << 16);
        lo[i*2]   = (unsigned)l0 | ((unsigned)l1 << 16);
        lo[i*2+1] = (unsigned)l2 | ((unsigned)l3 << 16);
    }
    char* dH = sm + offH + row * TSTRIDE + kh * 2;
    char* dL = sm + offL + row * TSTRIDE + kh * 2;
    #pragma unroll
    for (int j = 0; j < 4; j++) {
        *(uint4*)(dH + 16 * j) = *(uint4*)&hi[4*j];
        *(uint4*)(dL + 16 * j) = *(uint4*)&lo[4*j];
    }
}

// from bf16 global (stride HH)
__device__ __forceinline__ void fill_B(char* sm, int off, const __nv_bfloat16* src) {
    const int tid = threadIdx.x;
    const int row = tid >> 1;
    const int kh  = (tid & 1) * 32;
    const uint4* p = (const uint4*)(src + (size_t)row * HH + kh);
    char* d = sm + off + row * TSTRIDE + kh * 2;
    #pragma unroll
    for (int j = 0; j < 4; j++)
        *(uint4*)(d + 16 * j) = p[j];
}

// ---------------- warp-level 128x128x64 GEMM with hi/lo split (3 products) ----
// acc[mi][ni][4]: m16n8 fragments. Warp covers m64 x n32 at (mbase, nbase).
__device__ __forceinline__ void wgemm64(float acc[4][4][4],
                                        uint32_t aH, uint32_t aL,
                                        uint32_t bH, uint32_t bL,
                                        int lane, int mbase, int nbase) {
    const int arow = mbase + (lane & 15);
    const int acol8 = (lane >> 4);
    const int brow = nbase + ((lane >> 4) << 3) + (lane & 7);
    const int bcol8 = (lane >> 3) & 1;
    #pragma unroll
    for (int ks = 0; ks < 4; ks++) {
        uint32_t Ah[4][4], Al[4][4];
        #pragma unroll
        for (int mi = 0; mi < 4; mi++) {
            uint32_t off = (uint32_t)((arow + mi * 16) * TSTRIDE + (ks * 16 + acol8 * 8) * 2);
            ldsm4(Ah[mi], aH + off);
            ldsm4(Al[mi], aL + off);
        }
        uint32_t Bh[2][4], Bl[2][4];
        #pragma unroll
        for (int np = 0; np < 2; np++) {
            uint32_t off = (uint32_t)((brow + np * 16) * TSTRIDE + (ks * 16 + bcol8 * 8) * 2);
            ldsm4(Bh[np], bH + off);
            ldsm4(Bl[np], bL + off);
        }
        #pragma unroll
        for (int mi = 0; mi < 4; mi++)
            #pragma unroll
            for (int ni = 0; ni < 4; ni++) {
                const uint32_t* bh = &Bh[ni >> 1][(ni & 1) * 2];
                const uint32_t* bl = &Bl[ni >> 1][(ni & 1) * 2];
                mma16816(acc[mi][ni], Ah[mi], bh);
                mma16816(acc[mi][ni], Ah[mi], bl);
                mma16816(acc[mi][ni], Al[mi], bh);
            }
    }
}

__device__ __forceinline__ void zero_acc(float acc[4][4][4]) {
    #pragma unroll
    for (int i = 0; i < 4; i++)
        #pragma unroll
        for (int j = 0; j < 4; j++)
            #pragma unroll
            for (int e = 0; e < 4; e++) acc[i][j][e] = 0.f;
}

// store warp accumulators to dst[m*HH + nabs]
__device__ __forceinline__ void store_acc(float acc[4][4][4], float* dst,
                                          int lane, int mbase, int nabs) {
    const int r0 = mbase + (lane >> 2);
    const int c0 = nabs + (lane & 3) * 2;
    #pragma unroll
    for (int mi = 0; mi < 4; mi++)
        #pragma unroll
        for (int ni = 0; ni < 4; ni++) {
            float* p0 = dst + (size_t)(r0 + mi * 16) * HH + c0 + ni * 8;
            *(float2*)p0                      = make_float2(acc[mi][ni][0], acc[mi][ni][1]);
            *(float2*)(p0 + (size_t)8 * HH)   = make_float2(acc[mi][ni][2], acc[mi][ni][3]);
        }
}

// ---------------- convert kernels ----------------
__global__ void wconv_kernel(const float* __restrict__ Wi, const float* __restrict__ Wh) {
    __shared__ float tile[32][33];
    const int mat = blockIdx.z;
    const float* src = (mat == 0) ? Wi : (mat == 1) ? Wh
                     : (mat == 2) ? (Wi + (size_t)HH * HH) : (Wh + (size_t)HH * HH);
    const int n0 = blockIdx.x * 32, k0 = blockIdx.y * 32;
    const int tx = threadIdx.x, ty = threadIdx.y;   // 32 x 8
    #pragma unroll
    for (int i = 0; i < 32; i += 8)
        tile[ty + i][tx] = src[(size_t)(k0 + ty + i) * HH + n0 + tx];
    __syncthreads();
    #pragma unroll
    for (int i = 0; i < 32; i += 8) {
        float f = tile[tx][ty + i];                 // = W[k0+tx][n0+ty+i]
        unsigned short h, l;
        bsplit(f, h, l);
        size_t o = (size_t)(n0 + ty + i) * HH + k0 + tx;
        g_wt_hi[mat][o] = __ushort_as_bfloat16(h);
        g_wt_lo[mat][o] = __ushort_as_bfloat16(l);
    }
}

__global__ void xconv_kernel(const float* __restrict__ x) {
    size_t gid = (size_t)blockIdx.x * blockDim.x + threadIdx.x;
    size_t e = gid * 4;
    int k = (int)(e & (HH - 1));
    size_t q = e >> 10;                 // b*TT + t
    int b = (int)(q >> 8);
    int t = (int)(q & (TT - 1));
    float4 v = *(const float4*)(x + ((size_t)b * TT + t) * HH + k);
    unsigned short h0,l0,h1,l1,h2,l2,h3,l3;
    bsplit(v.x,h0,l0); bsplit(v.y,h1,l1); bsplit(v.z,h2,l2); bsplit(v.w,h3,l3);
    uint2 hv = make_uint2((unsigned)h0 | ((unsigned)h1<<16), (unsigned)h2 | ((unsigned)h3<<16));
    uint2 lv = make_uint2((unsigned)l0 | ((unsigned)l1<<16), (unsigned)l2 | ((unsigned)l3<<16));
    size_t dst = ((size_t)t * BB + b) * HH + k;
    *(uint2*)(g_xs_hi + dst) = hv;
    *(uint2*)(g_xs_lo + dst) = lv;
}

// ---------------- xp GEMM: g_xp = x @ Wi0 + bi0 (warp MMA) ----------------
#define TB (128 * TSTRIDE)            // 18432 bytes per tile
#define XP_SMEM (4 * TB)              // Ah, Al, Bh, Bl

__global__ void __launch_bounds__(NTHR)
xp_mma_kernel(const float* __restrict__ bi) {
    extern __shared__ char sm[];
    const uint32_t smb = smem_u32(sm);
    const int tid = threadIdx.x, wid = tid >> 5, lane = tid & 31;
    const int n0 = blockIdx.x * 128;
    const int r0 = blockIdx.y * 128;
    const int mbase = (wid >> 2) * 64, nbase = (wid & 3) * 32;

    float acc[4][4][4];
    zero_acc(acc);

    for (int s = 0; s < 16; s++) {
        const int koff = s * 64;
        fill_B(sm, 0 * TB, (const __nv_bfloat16*)(g_xs_hi + (size_t)r0 * HH + koff));
        fill_B(sm, 1 * TB, (const __nv_bfloat16*)(g_xs_lo + (size_t)r0 * HH + koff));
        fill_B(sm, 2 * TB, g_wt_hi[0] + (size_t)n0 * HH + koff);
        fill_B(sm, 3 * TB, g_wt_lo[0] + (size_t)n0 * HH + koff);
        __syncthreads();
        wgemm64(acc, smb + 0 * TB, smb + 1 * TB, smb + 2 * TB, smb + 3 * TB,
                lane, mbase, nbase);
        __syncthreads();
    }

    // add bias, write to g_xp
    const int r0w = r0 + mbase + (lane >> 2);
    const int c0 = n0 + nbase + (lane & 3) * 2;
    #pragma unroll
    for (int mi = 0; mi < 4; mi++)
        #pragma unroll
        for (int ni = 0; ni < 4; ni++) {
            const int c = c0 + ni * 8;
            float b0 = __ldg(bi + c), b1 = __ldg(bi + c + 1);
            float* p0 = g_xp + (size_t)(r0w + mi * 16) * HH + c;
            *(float2*)p0                    = make_float2(acc[mi][ni][0] + b0, acc[mi][ni][1] + b1);
            *(float2*)(p0 + (size_t)8 * HH) = make_float2(acc[mi][ni][2] + b0, acc[mi][ni][3] + b1);
        }
}

// ---------------- persistent recurrent kernel ----------------
// smem: A0h A0l A1h A1l | W0h W0l I1h I1l H1h H1l  (10 tiles)
#define RNN_SMEM (10 * TB)            // 184320 bytes

__global__ void __launch_bounds__(NTHR)
rnn_mma_kernel(const float* __restrict__ h0in,
               const float* __restrict__ bi,
               const float* __restrict__ bh,
               float* __restrict__ out)
{
    extern __shared__ char sm[];
    const uint32_t smb = smem_u32(sm);
    const int tid = threadIdx.x, wid = tid >> 5, lane = tid & 31;
    const int cta = blockIdx.x;
    const int gtid = cta * NTHR + tid;
    const int ntile = cta & 7, split = cta >> 3;
    const int n0 = ntile * 128, koff = split * 64;
    const int mbase = (wid >> 2) * 64, nbase = (wid & 3) * 32;

    const uint32_t A0H = smb + 0*TB, A0L = smb + 1*TB;
    const uint32_t A1H = smb + 2*TB, A1L = smb + 3*TB;
    const uint32_t W0H = smb + 4*TB, W0L = smb + 5*TB;
    const uint32_t I1H = smb + 6*TB, I1L = smb + 7*TB;
    const uint32_t H1H = smb + 8*TB, H1L = smb + 9*TB;

    // resident weight tiles (rows = n dim of W^T, cols = k slice)
    fill_B(sm, 4*TB, g_wt_hi[1] + (size_t)n0 * HH + koff);
    fill_B(sm, 5*TB, g_wt_lo[1] + (size_t)n0 * HH + koff);
    fill_B(sm, 6*TB, g_wt_hi[2] + (size_t)n0 * HH + koff);
    fill_B(sm, 7*TB, g_wt_lo[2] + (size_t)n0 * HH + koff);
    fill_B(sm, 8*TB, g_wt_hi[3] + (size_t)n0 * HH + koff);
    fill_B(sm, 9*TB, g_wt_lo[3] + (size_t)n0 * HH + koff);

    // init hidden state (broadcast over batch)
    for (int e = gtid; e < BB * HH; e += NCTA * NTHR) {
        const int hc = e & (HH - 1);
        g_h0[0][e] = h0in[hc];
        g_h1[0][e] = h0in[HH + hc];
    }
    grid_sync();

    for (int t = 0; t < TT; t++) {
        const int prev = t & 1;
        const int cur  = prev ^ 1;
        float acc2[4][4][4];          // layer-1 accumulator, lives A -> C

        // ---- phase A: D1 = h0_prev@Wh0 slice ; D2 = h1_prev@Wh1 slice ----
        {
            fill_A(sm, 0*TB, 1*TB, g_h0[prev], koff);
            fill_A(sm, 2*TB, 3*TB, g_h1[prev], koff);
            __syncthreads();
            float acc1[4][4][4];
            zero_acc(acc1);
            zero_acc(acc2);
            wgemm64(acc1, A0H, A0L, W0H, W0L, lane, mbase, nbase);
            wgemm64(acc2, A1H, A1L, H1H, H1L, lane, mbase, nbase);
            store_acc(acc1, g_part[split], lane, mbase, n0 + nbase);
        }
        grid_sync();

        // ---- phase B: h0_cur = tanh(xp[t] + bh0 + sum partials) ----
        {
            const int e = gtid * 4;
            const int n = e & (HH - 1);
            float4 acc = *(const float4*)(g_xp + (size_t)t * BB * HH + e);
            acc.x += bh[n];     acc.y += bh[n + 1];
            acc.z += bh[n + 2]; acc.w += bh[n + 3];
            #pragma unroll
            for (int s = 0; s < NSPLIT; s++) {
                float4 p = __ldcg((const float4*)(g_part[s] + e));
                acc.x += p.x; acc.y += p.y; acc.z += p.z; acc.w += p.w;
            }
            float4 r = make_float4(tanhf(acc.x), tanhf(acc.y), tanhf(acc.z), tanhf(acc.w));
            *(float4*)(g_h0[cur] + e) = r;
        }
        grid_sync();

        // ---- phase C: D2 += h0_cur@Wi1 slice ----
        {
            fill_A(sm, 0*TB, 1*TB, g_h0[cur], koff);
            __syncthreads();
            wgemm64(acc2, A0H, A0L, I1H, I1L, lane, mbase, nbase);
            store_acc(acc2, g_part[split], lane, mbase, n0 + nbase);
        }
        grid_sync();

        // ---- phase D: h1_cur = tanh(bi1 + bh1 + sum partials); write out ----
        {
            const int e = gtid * 4;
            const int n = e & (HH - 1);
            const int b = e >> 10;
            float4 acc;
            acc.x = bi[HH + n]     + bh[HH + n];
            acc.y = bi[HH + n + 1] + bh[HH + n + 1];
            acc.z = bi[HH + n + 2] + bh[HH + n + 2];
            acc.w = bi[HH + n + 3] + bh[HH + n + 3];
            #pragma unroll
            for (int s = 0; s < NSPLIT; s++) {
                float4 p = __ldcg((const float4*)(g_part[s] + e));
                acc.x += p.x; acc.y += p.y; acc.z += p.z; acc.w += p.w;
            }
            float4 r = make_float4(tanhf(acc.x), tanhf(acc.y), tanhf(acc.z), tanhf(acc.w));
            *(float4*)(g_h1[cur] + e) = r;
            *(float4*)(out + ((size_t)b * TT + t) * HH + n) = r;
        }
        grid_sync();
    }

    // finals: cur at t=255 is 0 for both layers
    float* hn = out + (size_t)BB * TT * HH;
    for (int e = gtid; e < BB * HH; e += NCTA * NTHR) {
        const int b = e >> 10;
        const int n = e & (HH - 1);
        hn[(size_t)(b * 2) * HH + n]     = __ldcg(g_h0[0] + e);
        hn[(size_t)(b * 2 + 1) * HH + n] = __ldcg(g_h1[0] + e);
    }
}

// ---------------- entry ----------------
extern "C" void kernel_launch(void* const* d_in, const int* in_sizes, int n_in,
                              void* d_out, int out_size)
{
    const float* x    = (const float*)d_in[0];
    const float* h0in = (const float*)d_in[1];
    const float* Wi   = (const float*)d_in[2];
    const float* bi   = (const float*)d_in[3];
    const float* Wh   = (const float*)d_in[4];
    const float* bh   = (const float*)d_in[5];
    float* out = (float*)d_out;

    cudaFuncSetAttribute(xp_mma_kernel,  cudaFuncAttributeMaxDynamicSharedMemorySize, XP_SMEM);
    cudaFuncSetAttribute(rnn_mma_kernel, cudaFuncAttributeMaxDynamicSharedMemorySize, RNN_SMEM);

    wconv_kernel<<<dim3(32, 32, 4), dim3(32, 8)>>>(Wi, Wh);
    xconv_kernel<<<(TT * BB * HH / 4) / 256, 256>>>(x);
    xp_mma_kernel<<<dim3(8, 256), NTHR, XP_SMEM>>>(bi);
    rnn_mma_kernel<<<NCTA, NTHR, RNN_SMEM>>>(h0in, bi, bh, out);
}